// round 1
// baseline (speedup 1.0000x reference)
#include <cuda_runtime.h>
#include <cuda_fp16.h>
#include <mma.h>

using namespace nvcuda;

#define BATCH 4096
#define NAG   32
#define DIN_  256
#define HID   128
#define NACT  32
#define MTOT  (BATCH*NAG)   // 131072 rows

// ---- static scratch (no cudaMalloc allowed) ----
__device__ __half g_h [(size_t)MTOT*HID];
__device__ __half g_v [(size_t)MTOT*HID];
__device__ __half g_q [(size_t)MTOT*HID];
__device__ __half g_k [(size_t)MTOT*HID];
__device__ __half g_ao[(size_t)MTOT*HID];

// ============================================================
// Generic GEMM: C[M,NC] = act(A[M,K] @ W[K,NC] + bias)
//   A: half (or fp32, converted on load), W/bias: fp32 -> half in smem
//   CTA: 256 thr = 8 warps (4x2), CTA tile 128 x NC, full K resident
// ============================================================
template<int K_DIM, int NC, bool RELU, bool IN_F32, bool OUT_F32>
__global__ __launch_bounds__(256)
void gemm_kernel(const void* __restrict__ Av, const float* __restrict__ W,
                 const float* __restrict__ bias, void* __restrict__ Cv) {
    constexpr int MT   = 128;
    constexpr int LDA  = K_DIM + 8;   // half, rows 16B-aligned, bank-shifted
    constexpr int LDW  = NC + 8;
    constexpr int WNC  = NC / 2;      // warp cols
    constexpr int NFX  = WNC / 16;    // frags along N
    constexpr int LDSO = WNC + 4;     // fp32 scratch ld

    extern __shared__ char smem[];
    __half* sA    = (__half*)smem;                       // [MT][LDA]
    __half* sW    = sA + MT*LDA;                          // [K_DIM][LDW]
    float*  sBias = (float*)(sW + (size_t)K_DIM*LDW);     // [16][NC]
    float*  sOut  = sBias + 16*NC;                        // [8][32][LDSO]

    const int tid  = threadIdx.x;
    const int wid  = tid >> 5;
    const int lane = tid & 31;
    const size_t row0 = (size_t)blockIdx.x * MT;

    // ---- stage A tile ----
    if (IN_F32) {
        const float* A = (const float*)Av;
        constexpr int CPR = K_DIM/8;
        for (int i = tid; i < MT*CPR; i += 256) {
            int r = i / CPR, c = (i % CPR) * 8;
            const float4* p = (const float4*)(A + (row0 + r)*K_DIM + c);
            float4 f0 = p[0], f1 = p[1];
            __half2* d = (__half2*)(sA + r*LDA + c);
            d[0] = __floats2half2_rn(f0.x, f0.y);
            d[1] = __floats2half2_rn(f0.z, f0.w);
            d[2] = __floats2half2_rn(f1.x, f1.y);
            d[3] = __floats2half2_rn(f1.z, f1.w);
        }
    } else {
        const __half* A = (const __half*)Av;
        constexpr int CPR = K_DIM/8;
        for (int i = tid; i < MT*CPR; i += 256) {
            int r = i / CPR, c = (i % CPR) * 8;
            *(uint4*)(sA + r*LDA + c) = *(const uint4*)(A + (row0 + r)*K_DIM + c);
        }
    }
    // ---- stage W (fp32 -> half) ----
    {
        constexpr int CPR = NC/4;
        for (int i = tid; i < K_DIM*CPR; i += 256) {
            int r = i / CPR, c = (i % CPR) * 4;
            float4 f = *(const float4*)(W + (size_t)r*NC + c);
            __half2* d = (__half2*)(sW + r*LDW + c);
            d[0] = __floats2half2_rn(f.x, f.y);
            d[1] = __floats2half2_rn(f.z, f.w);
        }
    }
    // ---- bias tile replicated over 16 rows (accumulator init trick) ----
    for (int i = tid; i < 16*NC; i += 256) sBias[i] = bias[i % NC];
    __syncthreads();

    const int wy = wid >> 1;        // 0..3 : row block of 32
    const int wx = wid & 1;         // 0..1 : col block of WNC

    wmma::fragment<wmma::accumulator,16,16,16,float> acc[2][NFX];
    #pragma unroll
    for (int i = 0; i < 2; i++)
        #pragma unroll
        for (int j = 0; j < NFX; j++)
            wmma::load_matrix_sync(acc[i][j], sBias + wx*WNC + j*16, NC, wmma::mem_row_major);

    #pragma unroll
    for (int k = 0; k < K_DIM; k += 16) {
        wmma::fragment<wmma::matrix_a,16,16,16,__half,wmma::row_major> a[2];
        wmma::load_matrix_sync(a[0], sA + (wy*32     )*LDA + k, LDA);
        wmma::load_matrix_sync(a[1], sA + (wy*32 + 16)*LDA + k, LDA);
        #pragma unroll
        for (int j = 0; j < NFX; j++) {
            wmma::fragment<wmma::matrix_b,16,16,16,__half,wmma::row_major> bf;
            wmma::load_matrix_sync(bf, sW + k*LDW + wx*WNC + j*16, LDW);
            wmma::mma_sync(acc[0][j], a[0], bf, acc[0][j]);
            wmma::mma_sync(acc[1][j], a[1], bf, acc[1][j]);
        }
    }

    // ---- epilogue: relu on fragments, roundtrip via smem for dtype convert ----
    float* myOut = sOut + (size_t)wid * 32 * LDSO;
    #pragma unroll
    for (int i = 0; i < 2; i++)
        #pragma unroll
        for (int j = 0; j < NFX; j++) {
            if (RELU) {
                #pragma unroll
                for (int e = 0; e < acc[i][j].num_elements; e++)
                    acc[i][j].x[e] = fmaxf(acc[i][j].x[e], 0.0f);
            }
            wmma::store_matrix_sync(myOut + i*16*LDSO + j*16, acc[i][j], LDSO, wmma::mem_row_major);
        }
    __syncwarp();

    const size_t rbase = row0 + (size_t)wy*32;
    if (OUT_F32) {
        float* C = (float*)Cv;
        for (int i = lane; i < 32*WNC; i += 32) {
            int r = i / WNC, c = i % WNC;
            C[(rbase + r)*NC + wx*WNC + c] = myOut[r*LDSO + c];
        }
    } else {
        __half* C = (__half*)Cv;
        for (int i = lane; i < 32*WNC; i += 32) {
            int r = i / WNC, c = i % WNC;
            C[(rbase + r)*NC + wx*WNC + c] = __float2half(myOut[r*LDSO + c]);
        }
    }
}

// ============================================================
// Fused attention: per-warp batch.  S = Q K^T (wmma), fp32 masked
// softmax (exact -9e15 semantics of the reference), O = Att V (wmma)
// block: 128 thr = 4 warps = 4 batches; grid = BATCH/4
// ============================================================
__global__ __launch_bounds__(128)
void attn_kernel(const __half* __restrict__ Q, const __half* __restrict__ K,
                 const __half* __restrict__ V, const float* __restrict__ mask,
                 __half* __restrict__ O) {
    constexpr int LDH   = 136;  // half tile ld
    constexpr int LDSS  = 36;   // S fp32 ld
    constexpr int LDATT = 40;   // Att half ld
    constexpr int LDO   = 132;  // O fp32 scratch ld
    constexpr int WARP_BYTES = 3*32*LDH*2 + 32*LDSS*4 + 32*LDATT*2;  // 33280

    extern __shared__ char smem[];
    const int wid  = threadIdx.x >> 5;
    const int lane = threadIdx.x & 31;
    char* base = smem + (size_t)wid * WARP_BYTES;
    __half* sQ   = (__half*)base;
    __half* sK   = sQ + 32*LDH;
    __half* sV   = sK + 32*LDH;
    float*  sS   = (float*)(sV + 32*LDH);
    __half* sAtt = (__half*)(sS + 32*LDSS);
    float*  sO   = (float*)sQ;            // overlays sQ+sK (free after S)

    const int b = blockIdx.x * 4 + wid;
    const size_t off = (size_t)b * NAG * HID;

    for (int i = lane; i < NAG*HID/8; i += 32) {
        int r = i >> 4, c = (i & 15) << 3;
        *(uint4*)(sQ + r*LDH + c) = *(const uint4*)(Q + off + r*HID + c);
        *(uint4*)(sK + r*LDH + c) = *(const uint4*)(K + off + r*HID + c);
        *(uint4*)(sV + r*LDH + c) = *(const uint4*)(V + off + r*HID + c);
    }
    __syncwarp();

    // ---- S = Q @ K^T  (32x32, K=128) ----
    {
        wmma::fragment<wmma::accumulator,16,16,16,float> acc[2][2];
        #pragma unroll
        for (int i = 0; i < 2; i++)
            #pragma unroll
            for (int j = 0; j < 2; j++) wmma::fill_fragment(acc[i][j], 0.0f);
        #pragma unroll
        for (int k = 0; k < HID; k += 16) {
            wmma::fragment<wmma::matrix_a,16,16,16,__half,wmma::row_major> a[2];
            wmma::load_matrix_sync(a[0], sQ +  0*LDH + k, LDH);
            wmma::load_matrix_sync(a[1], sQ + 16*LDH + k, LDH);
            wmma::fragment<wmma::matrix_b,16,16,16,__half,wmma::col_major> bf[2];
            wmma::load_matrix_sync(bf[0], sK +  0*LDH + k, LDH);
            wmma::load_matrix_sync(bf[1], sK + 16*LDH + k, LDH);
            #pragma unroll
            for (int i = 0; i < 2; i++)
                #pragma unroll
                for (int j = 0; j < 2; j++) wmma::mma_sync(acc[i][j], a[i], bf[j], acc[i][j]);
        }
        #pragma unroll
        for (int i = 0; i < 2; i++)
            #pragma unroll
            for (int j = 0; j < 2; j++)
                wmma::store_matrix_sync(sS + i*16*LDSS + j*16, acc[i][j], LDSS, wmma::mem_row_major);
    }
    __syncwarp();

    // ---- masked softmax, row = lane, fp32 (exact reference semantics) ----
    {
        const float* mrow = mask + (size_t)b*NAG*NAG + lane*NAG;
        float e[NAG];
        float mx = -3.0e38f;
        #pragma unroll
        for (int j = 0; j < NAG; j++) {
            float m = mrow[j];
            float l = sS[lane*LDSS + j] * m - 9.0e15f * (1.0f - m);
            e[j] = l;
            mx = fmaxf(mx, l);
        }
        float sum = 0.0f;
        #pragma unroll
        for (int j = 0; j < NAG; j++) { float t = expf(e[j] - mx); e[j] = t; sum += t; }
        float inv = 1.0f / sum;
        #pragma unroll
        for (int j = 0; j < NAG; j++) sAtt[lane*LDATT + j] = __float2half(e[j] * inv);
    }
    __syncwarp();

    // ---- O = Att @ V  (32x128, K=32) ----
    {
        wmma::fragment<wmma::accumulator,16,16,16,float> acc[2][8];
        #pragma unroll
        for (int i = 0; i < 2; i++)
            #pragma unroll
            for (int j = 0; j < 8; j++) wmma::fill_fragment(acc[i][j], 0.0f);
        #pragma unroll
        for (int k = 0; k < NAG; k += 16) {
            wmma::fragment<wmma::matrix_a,16,16,16,__half,wmma::row_major> a[2];
            wmma::load_matrix_sync(a[0], sAtt +  0*LDATT + k, LDATT);
            wmma::load_matrix_sync(a[1], sAtt + 16*LDATT + k, LDATT);
            #pragma unroll
            for (int j = 0; j < 8; j++) {
                wmma::fragment<wmma::matrix_b,16,16,16,__half,wmma::row_major> bf;
                wmma::load_matrix_sync(bf, sV + k*LDH + j*16, LDH);
                wmma::mma_sync(acc[0][j], a[0], bf, acc[0][j]);
                wmma::mma_sync(acc[1][j], a[1], bf, acc[1][j]);
            }
        }
        #pragma unroll
        for (int i = 0; i < 2; i++)
            #pragma unroll
            for (int j = 0; j < 8; j++)
                wmma::store_matrix_sync(sO + i*16*LDO + j*16, acc[i][j], LDO, wmma::mem_row_major);
    }
    __syncwarp();

    for (int i = lane; i < NAG*HID; i += 32) {
        int r = i >> 7, c = i & 127;
        O[off + i] = __float2half(sO[r*LDO + c]);
    }
}

// ============================================================
extern "C" void kernel_launch(void* const* d_in, const int* in_sizes, int n_in,
                              void* d_out, int out_size) {
    const float* x     = (const float*)d_in[0];
    const float* mask  = (const float*)d_in[1];
    const float* enc_w = (const float*)d_in[2];
    const float* enc_b = (const float*)d_in[3];
    // per attention block, metadata order: vw, vb, kw, kb, qw, qb, ow, ob
    const float* a1_vw = (const float*)d_in[4];
    const float* a1_vb = (const float*)d_in[5];
    const float* a1_kw = (const float*)d_in[6];
    const float* a1_kb = (const float*)d_in[7];
    const float* a1_qw = (const float*)d_in[8];
    const float* a1_qb = (const float*)d_in[9];
    const float* a1_ow = (const float*)d_in[10];
    const float* a1_ob = (const float*)d_in[11];
    const float* a2_vw = (const float*)d_in[12];
    const float* a2_vb = (const float*)d_in[13];
    const float* a2_kw = (const float*)d_in[14];
    const float* a2_kb = (const float*)d_in[15];
    const float* a2_qw = (const float*)d_in[16];
    const float* a2_qb = (const float*)d_in[17];
    const float* a2_ow = (const float*)d_in[18];
    const float* a2_ob = (const float*)d_in[19];
    const float* q_w   = (const float*)d_in[20];
    const float* q_b   = (const float*)d_in[21];
    float* out = (float*)d_out;

    void *ph, *pv, *pq, *pk, *pao;
    cudaGetSymbolAddress(&ph,  g_h);
    cudaGetSymbolAddress(&pv,  g_v);
    cudaGetSymbolAddress(&pq,  g_q);
    cudaGetSymbolAddress(&pk,  g_k);
    cudaGetSymbolAddress(&pao, g_ao);

    // smem sizes (mirror kernel constexpr layout)
    const size_t smEnc = 128*(256+8)*2 + 256*(128+8)*2 + 16*128*4 + 8*32*(64+4)*4; // 215040
    const size_t smMid = 128*(128+8)*2 + 128*(128+8)*2 + 16*128*4 + 8*32*(64+4)*4; // 147456
    const size_t smFin = 128*(128+8)*2 + 128*( 32+8)*2 + 16* 32*4 + 8*32*(16+4)*4; //  67584
    const size_t smAtt = 4 * (3*32*136*2 + 32*36*4 + 32*40*2);                     // 133120

    auto encK = gemm_kernel<256,128,true ,true ,false>;
    auto midK = gemm_kernel<128,128,true ,false,false>;
    auto finK = gemm_kernel<128, 32,false,false,true >;
    cudaFuncSetAttribute(encK, cudaFuncAttributeMaxDynamicSharedMemorySize, (int)smEnc);
    cudaFuncSetAttribute(midK, cudaFuncAttributeMaxDynamicSharedMemorySize, (int)smMid);
    cudaFuncSetAttribute(finK, cudaFuncAttributeMaxDynamicSharedMemorySize, (int)smFin);
    cudaFuncSetAttribute(attn_kernel, cudaFuncAttributeMaxDynamicSharedMemorySize, (int)smAtt);

    const int grid = MTOT / 128;   // 1024

    // encoder
    encK<<<grid,256,smEnc>>>(x, enc_w, enc_b, ph);

    // block 1
    midK<<<grid,256,smMid>>>(ph, a1_vw, a1_vb, pv);
    midK<<<grid,256,smMid>>>(ph, a1_qw, a1_qb, pq);
    midK<<<grid,256,smMid>>>(ph, a1_kw, a1_kb, pk);
    attn_kernel<<<BATCH/4,128,smAtt>>>((const __half*)pq,(const __half*)pk,(const __half*)pv, mask, (__half*)pao);
    midK<<<grid,256,smMid>>>(pao, a1_ow, a1_ob, ph);

    // block 2
    midK<<<grid,256,smMid>>>(ph, a2_vw, a2_vb, pv);
    midK<<<grid,256,smMid>>>(ph, a2_qw, a2_qb, pq);
    midK<<<grid,256,smMid>>>(ph, a2_kw, a2_kb, pk);
    attn_kernel<<<BATCH/4,128,smAtt>>>((const __half*)pq,(const __half*)pk,(const __half*)pv, mask, (__half*)pao);
    midK<<<grid,256,smMid>>>(pao, a2_ow, a2_ob, ph);

    // final Q head (fp32 out, no relu)
    finK<<<grid,256,smFin>>>(ph, q_w, q_b, out);
}

// round 6
// speedup vs baseline: 1.4409x; 1.4409x over previous
#include <cuda_runtime.h>
#include <cuda_fp16.h>
#include <mma.h>
#include <cstdint>

using namespace nvcuda;

#define BATCH 4096
#define NAG   32
#define DIN_  256
#define HID   128
#define NACT  32
#define MTOT  (BATCH*NAG)   // 131072 rows

// ---- static scratch (no cudaMalloc allowed) ----
__device__ __half g_h [(size_t)MTOT*HID];
__device__ __half g_v [(size_t)MTOT*HID];
__device__ __half g_q [(size_t)MTOT*HID];
__device__ __half g_k [(size_t)MTOT*HID];
__device__ __half g_ao[(size_t)MTOT*HID];

// ============================================================
// Big-tile wmma GEMM:  Cm[M,NC] = act(A[M,K] @ Wm[K,NC] + bm), m < NM
//   CTA tile 256 x NC, 8 warps, warp tile 64 x (NC/2)
//   A staged once; NM weight sets resident -> V/Q/K fusion
//   Epilogue: fp32 acc -> half acc fragment -> direct gmem store
// ============================================================
template<int K_DIM, int NC, int NM, bool RELU, bool IN_F32, bool OUT_F32>
__global__ __launch_bounds__(256, 1)
void gemm_big(const void* __restrict__ Av,
              const float* __restrict__ W0, const float* __restrict__ W1,
              const float* __restrict__ W2,
              const float* __restrict__ b0, const float* __restrict__ b1,
              const float* __restrict__ b2,
              void* __restrict__ C0, void* __restrict__ C1, void* __restrict__ C2) {
    constexpr int MT   = 256;
    constexpr int LDA  = K_DIM + 8;     // halves
    constexpr int LDW  = NC + 8;        // halves
    constexpr int WNC  = NC / 2;        // warp cols
    constexpr int NFX  = WNC / 16;      // 4 for NC=128, 1 for NC=32
    constexpr int KS   = K_DIM / 16;

    extern __shared__ char smem[];
    __half* sA    = (__half*)smem;                          // [MT][LDA]
    __half* sW    = sA + (size_t)MT * LDA;                  // NM x [K_DIM][LDW]
    float*  sBias = (float*)(sW + (size_t)NM * K_DIM * LDW);// NM x [16][NC]

    const int tid  = threadIdx.x;
    const int wid  = tid >> 5;
    const size_t row0 = (size_t)blockIdx.x * MT;

    const float* Ws[3] = {W0, W1, W2};
    const float* bs[3] = {b0, b1, b2};
    void*        Cs[3] = {C0, C1, C2};

    // ---- stage A ----
    constexpr int CPR = K_DIM / 8;
    if (IN_F32) {
        const float* A = (const float*)Av;
        for (int i = tid; i < MT * CPR; i += 256) {
            int r = i / CPR, c = (i % CPR) * 8;
            const float4* p = (const float4*)(A + (row0 + r) * K_DIM + c);
            float4 f0 = p[0], f1 = p[1];
            __half2* d = (__half2*)(sA + r * LDA + c);
            d[0] = __floats2half2_rn(f0.x, f0.y);
            d[1] = __floats2half2_rn(f0.z, f0.w);
            d[2] = __floats2half2_rn(f1.x, f1.y);
            d[3] = __floats2half2_rn(f1.z, f1.w);
        }
    } else {
        const __half* A = (const __half*)Av;
        for (int i = tid; i < MT * CPR; i += 256) {
            int r = i / CPR, c = (i % CPR) * 8;
            *(uint4*)(sA + r * LDA + c) = *(const uint4*)(A + (row0 + r) * K_DIM + c);
        }
    }
    // ---- stage weights (fp32 -> half) ----
    for (int m = 0; m < NM; m++) {
        const float* W = Ws[m];
        __half* sWm = sW + (size_t)m * K_DIM * LDW;
        constexpr int WCPR = NC / 4;
        for (int i = tid; i < K_DIM * WCPR; i += 256) {
            int r = i / WCPR, c = (i % WCPR) * 4;
            float4 f = *(const float4*)(W + (size_t)r * NC + c);
            __half2* d = (__half2*)(sWm + r * LDW + c);
            d[0] = __floats2half2_rn(f.x, f.y);
            d[1] = __floats2half2_rn(f.z, f.w);
        }
        float* sBm = sBias + m * 16 * NC;
        for (int i = tid; i < 16 * NC; i += 256) sBm[i] = bs[m][i % NC];
    }
    __syncthreads();

    const int wy = wid >> 1;        // 0..3 : 64-row block
    const int wx = wid & 1;         // 0..1 : WNC-col block

    for (int m = 0; m < NM; m++) {
        const __half* sWm = sW + (size_t)m * K_DIM * LDW;
        const float*  sBm = sBias + m * 16 * NC;

        wmma::fragment<wmma::accumulator,16,16,16,float> acc[4][NFX];
        #pragma unroll
        for (int j = 0; j < NFX; j++) {
            wmma::load_matrix_sync(acc[0][j], sBm + wx*WNC + j*16, NC, wmma::mem_row_major);
            #pragma unroll
            for (int i = 1; i < 4; i++) acc[i][j] = acc[0][j];
        }

        #pragma unroll
        for (int ks = 0; ks < KS; ks++) {
            const int k = ks * 16;
            wmma::fragment<wmma::matrix_a,16,16,16,__half,wmma::row_major> a[4];
            #pragma unroll
            for (int i = 0; i < 4; i++)
                wmma::load_matrix_sync(a[i], sA + (wy*64 + i*16)*LDA + k, LDA);
            #pragma unroll
            for (int j = 0; j < NFX; j++) {
                wmma::fragment<wmma::matrix_b,16,16,16,__half,wmma::row_major> bf;
                wmma::load_matrix_sync(bf, sWm + k*LDW + wx*WNC + j*16, LDW);
                #pragma unroll
                for (int i = 0; i < 4; i++)
                    wmma::mma_sync(acc[i][j], a[i], bf, acc[i][j]);
            }
        }

        // ---- epilogue: relu (+cvt) on fragments, direct gmem store ----
        const size_t rb = row0 + (size_t)wy * 64;
        if (OUT_F32) {
            float* C = (float*)Cs[m];
            #pragma unroll
            for (int i = 0; i < 4; i++)
                #pragma unroll
                for (int j = 0; j < NFX; j++) {
                    if (RELU) {
                        #pragma unroll
                        for (int e = 0; e < acc[i][j].num_elements; e++)
                            acc[i][j].x[e] = fmaxf(acc[i][j].x[e], 0.0f);
                    }
                    wmma::store_matrix_sync(C + (rb + i*16)*NC + wx*WNC + j*16,
                                            acc[i][j], NC, wmma::mem_row_major);
                }
        } else {
            __half* C = (__half*)Cs[m];
            #pragma unroll
            for (int i = 0; i < 4; i++)
                #pragma unroll
                for (int j = 0; j < NFX; j++) {
                    wmma::fragment<wmma::accumulator,16,16,16,__half> hf;
                    #pragma unroll
                    for (int e = 0; e < acc[i][j].num_elements; e++) {
                        float v = acc[i][j].x[e];
                        if (RELU) v = fmaxf(v, 0.0f);
                        hf.x[e] = __float2half(v);
                    }
                    wmma::store_matrix_sync(C + (rb + i*16)*NC + wx*WNC + j*16,
                                            hf, NC, wmma::mem_row_major);
                }
        }
    }
}

// ============================================================
// Attention: per-warp batch (8 warps / CTA). S=QK^T (wmma), fp32 masked
// softmax (exact -9e15 semantics), O=Att@V (wmma).
// Overlays: V over Q, Att over S, O fp32 staging over K.
// ============================================================
__global__ __launch_bounds__(256)
void attn_kernel(const __half* __restrict__ Q, const __half* __restrict__ K,
                 const __half* __restrict__ V, const float* __restrict__ mask,
                 __half* __restrict__ O) {
    constexpr int LDH   = 136;
    constexpr int LDSS  = 36;
    constexpr int LDATT = 40;
    constexpr int WB = 2 * 32 * LDH * 2 + 32 * LDSS * 4;  // 22016 B / warp

    extern __shared__ char smem[];
    const int wid  = threadIdx.x >> 5;
    const int lane = threadIdx.x & 31;
    char* base = smem + (size_t)wid * WB;
    __half* sQ   = (__half*)base;              // later: V
    __half* sK   = sQ + 32 * LDH;              // later: O fp32 staging (16x132)
    float*  sS   = (float*)(sK + 32 * LDH);
    __half* sAtt = (__half*)sS;                // overlay (lockstep-safe)

    const int b = blockIdx.x * 8 + wid;
    const size_t off = (size_t)b * NAG * HID;

    for (int i = lane; i < NAG * HID / 8; i += 32) {
        int r = i >> 4, c = (i & 15) << 3;
        *(uint4*)(sQ + r * LDH + c) = *(const uint4*)(Q + off + r * HID + c);
        *(uint4*)(sK + r * LDH + c) = *(const uint4*)(K + off + r * HID + c);
    }
    __syncwarp();

    // ---- S = Q @ K^T ----
    {
        wmma::fragment<wmma::accumulator,16,16,16,float> acc[2][2];
        #pragma unroll
        for (int i = 0; i < 2; i++)
            #pragma unroll
            for (int j = 0; j < 2; j++) wmma::fill_fragment(acc[i][j], 0.0f);
        #pragma unroll
        for (int k = 0; k < HID; k += 16) {
            wmma::fragment<wmma::matrix_a,16,16,16,__half,wmma::row_major> a[2];
            wmma::load_matrix_sync(a[0], sQ +  0*LDH + k, LDH);
            wmma::load_matrix_sync(a[1], sQ + 16*LDH + k, LDH);
            wmma::fragment<wmma::matrix_b,16,16,16,__half,wmma::col_major> bf[2];
            wmma::load_matrix_sync(bf[0], sK +  0*LDH + k, LDH);
            wmma::load_matrix_sync(bf[1], sK + 16*LDH + k, LDH);
            #pragma unroll
            for (int i = 0; i < 2; i++)
                #pragma unroll
                for (int j = 0; j < 2; j++) wmma::mma_sync(acc[i][j], a[i], bf[j], acc[i][j]);
        }
        #pragma unroll
        for (int i = 0; i < 2; i++)
            #pragma unroll
            for (int j = 0; j < 2; j++)
                wmma::store_matrix_sync(sS + i*16*LDSS + j*16, acc[i][j], LDSS, wmma::mem_row_major);
    }
    __syncwarp();

    // ---- masked softmax (exact reference semantics), row = lane ----
    {
        const float* mrow = mask + (size_t)b * NAG * NAG + lane * NAG;
        float e[NAG];
        float mx = -3.0e38f;
        #pragma unroll
        for (int j = 0; j < NAG; j++) {
            float m = mrow[j];
            float l = sS[lane * LDSS + j] * m - 9.0e15f * (1.0f - m);
            e[j] = l;
            mx = fmaxf(mx, l);
        }
        float sum = 0.0f;
        #pragma unroll
        for (int j = 0; j < NAG; j++) { float t = expf(e[j] - mx); e[j] = t; sum += t; }
        float inv = 1.0f / sum;
        #pragma unroll
        for (int j = 0; j < NAG; j++) sAtt[lane * LDATT + j] = __float2half(e[j] * inv);
    }
    __syncwarp();

    // ---- load V into sQ (Q dead) ----
    __half* sV = sQ;
    for (int i = lane; i < NAG * HID / 8; i += 32) {
        int r = i >> 4, c = (i & 15) << 3;
        *(uint4*)(sV + r * LDH + c) = *(const uint4*)(V + off + r * HID + c);
    }
    __syncwarp();

    // ---- O = Att @ V, staged through sK (dead) ----
    {
        wmma::fragment<wmma::accumulator,16,16,16,float> acc[2][8];
        #pragma unroll
        for (int i = 0; i < 2; i++)
            #pragma unroll
            for (int j = 0; j < 8; j++) wmma::fill_fragment(acc[i][j], 0.0f);
        #pragma unroll
        for (int k = 0; k < NAG; k += 16) {
            wmma::fragment<wmma::matrix_a,16,16,16,__half,wmma::row_major> a[2];
            wmma::load_matrix_sync(a[0], sAtt +  0*LDATT + k, LDATT);
            wmma::load_matrix_sync(a[1], sAtt + 16*LDATT + k, LDATT);
            #pragma unroll
            for (int j = 0; j < 8; j++) {
                wmma::fragment<wmma::matrix_b,16,16,16,__half,wmma::row_major> bf;
                wmma::load_matrix_sync(bf, sV + k*LDH + j*16, LDH);
                wmma::mma_sync(acc[0][j], a[0], bf, acc[0][j]);
                wmma::mma_sync(acc[1][j], a[1], bf, acc[1][j]);
            }
        }
        float* stg = (float*)sK;   // 16 x 132 fp32 = 8448 B <= 8704
        #pragma unroll
        for (int i = 0; i < 2; i++) {
            __syncwarp();
            #pragma unroll
            for (int j = 0; j < 8; j++)
                wmma::store_matrix_sync(stg + j*16, acc[i][j], 132, wmma::mem_row_major);
            __syncwarp();
            #pragma unroll
            for (int u = 0; u < 16; u++) {
                float4 f = *(float4*)(stg + u*132 + lane*4);
                __half2 h0 = __floats2half2_rn(f.x, f.y);
                __half2 h1 = __floats2half2_rn(f.z, f.w);
                __half2* dst = (__half2*)(O + off + (size_t)(i*16 + u)*HID + lane*4);
                dst[0] = h0; dst[1] = h1;
            }
        }
    }
}

// ============================================================
extern "C" void kernel_launch(void* const* d_in, const int* in_sizes, int n_in,
                              void* d_out, int out_size) {
    const float* x     = (const float*)d_in[0];
    const float* mask  = (const float*)d_in[1];
    const float* enc_w = (const float*)d_in[2];
    const float* enc_b = (const float*)d_in[3];
    const float* a1_vw = (const float*)d_in[4];
    const float* a1_vb = (const float*)d_in[5];
    const float* a1_kw = (const float*)d_in[6];
    const float* a1_kb = (const float*)d_in[7];
    const float* a1_qw = (const float*)d_in[8];
    const float* a1_qb = (const float*)d_in[9];
    const float* a1_ow = (const float*)d_in[10];
    const float* a1_ob = (const float*)d_in[11];
    const float* a2_vw = (const float*)d_in[12];
    const float* a2_vb = (const float*)d_in[13];
    const float* a2_kw = (const float*)d_in[14];
    const float* a2_kb = (const float*)d_in[15];
    const float* a2_qw = (const float*)d_in[16];
    const float* a2_qb = (const float*)d_in[17];
    const float* a2_ow = (const float*)d_in[18];
    const float* a2_ob = (const float*)d_in[19];
    const float* q_w   = (const float*)d_in[20];
    const float* q_b   = (const float*)d_in[21];
    float* out = (float*)d_out;

    void *ph, *pv, *pq, *pk, *pao;
    cudaGetSymbolAddress(&ph,  g_h);
    cudaGetSymbolAddress(&pv,  g_v);
    cudaGetSymbolAddress(&pq,  g_q);
    cudaGetSymbolAddress(&pk,  g_k);
    cudaGetSymbolAddress(&pao, g_ao);

    auto encK = gemm_big<256,128,1,true ,true ,false>;
    auto qkvK = gemm_big<128,128,3,true ,false,false>;
    auto opK  = gemm_big<128,128,1,true ,false,false>;
    auto finK = gemm_big<128, 32,1,false,false,true >;

    // smem byte sizes (mirror kernel layout)
    const size_t smEnc = (size_t)256*264*2 + 256*136*2 + 16*128*4;          // 212992
    const size_t smQkv = (size_t)256*136*2 + 3*128*136*2 + 3*16*128*4;      // 198656
    const size_t smOp  = (size_t)256*136*2 + 128*136*2 + 16*128*4;          // 112640
    const size_t smFin = (size_t)256*136*2 + 128*40*2  + 16*32*4;           //  81920
    const size_t smAtt = (size_t)8 * 22016;                                 // 176128
    cudaFuncSetAttribute(encK, cudaFuncAttributeMaxDynamicSharedMemorySize, (int)smEnc);
    cudaFuncSetAttribute(qkvK, cudaFuncAttributeMaxDynamicSharedMemorySize, (int)smQkv);
    cudaFuncSetAttribute(opK,  cudaFuncAttributeMaxDynamicSharedMemorySize, (int)smOp);
    cudaFuncSetAttribute(finK, cudaFuncAttributeMaxDynamicSharedMemorySize, (int)smFin);
    cudaFuncSetAttribute(attn_kernel, cudaFuncAttributeMaxDynamicSharedMemorySize, (int)smAtt);

    const int grid = MTOT / 256;   // 512

    // encoder
    encK<<<grid,256,smEnc>>>(x, enc_w,0,0, enc_b,0,0, ph,0,0);

    // block 1: fused V/Q/K, attention, out-proj
    qkvK<<<grid,256,smQkv>>>(ph, a1_vw,a1_qw,a1_kw, a1_vb,a1_qb,a1_kb, pv,pq,pk);
    attn_kernel<<<BATCH/8,256,smAtt>>>((const __half*)pq,(const __half*)pk,
                                       (const __half*)pv, mask, (__half*)pao);
    opK<<<grid,256,smOp>>>(pao, a1_ow,0,0, a1_ob,0,0, ph,0,0);

    // block 2
    qkvK<<<grid,256,smQkv>>>(ph, a2_vw,a2_qw,a2_kw, a2_vb,a2_qb,a2_kb, pv,pq,pk);
    attn_kernel<<<BATCH/8,256,smAtt>>>((const __half*)pq,(const __half*)pk,
                                       (const __half*)pv, mask, (__half*)pao);
    opK<<<grid,256,smOp>>>(pao, a2_ow,0,0, a2_ob,0,0, ph,0,0);

    // final head (fp32 out, no relu)
    finK<<<grid,256,smFin>>>(ph, q_w,0,0, q_b,0,0, out,0,0);
}